// round 5
// baseline (speedup 1.0000x reference)
#include <cuda_runtime.h>

// Problem: N=65536 rows. Per row n:
//   m = max_k |dot(x[n,k,:], y[n,0,:])|   (K=1024, D=4)
//   if m > 0.9999999 -> m = 1.0   (cost >= 0, so LOWER clamp is dead)
//   d[n] = 2*acos(m)              (acos monotone decreasing => min over k of
//                                  2*acos(cost) == 2*acos(max_k cost))
// out = sum(d) / N
//
// Inputs: d_in[0]=y (N,1,4) f32, d_in[1]=w_y (UNUSED), d_in[2]=x (N,K,4) f32.
// Output: 1 f32 scalar.
//
// R2 structure (measured fastest): 8192 HW-scheduled blocks, warp-per-row,
// single-level last-block ticket reduction. This round's single change:
// __ldcs -> __ldg A/B on the streaming loads.

#define N_ROWS   65536
#define K_DIM    1024
#define WARPS_PER_BLOCK 8
#define THREADS  (WARPS_PER_BLOCK * 32)
#define NBLOCKS  (N_ROWS / WARPS_PER_BLOCK)   // 8192

__device__ float        g_partials[NBLOCKS];
__device__ unsigned int g_ticket = 0;          // self-resetting each launch

__global__ __launch_bounds__(THREADS)
void fused_kernel(const float* __restrict__ y,
                  const float* __restrict__ x,
                  float* __restrict__ out)
{
    const int warp_in_blk = threadIdx.x >> 5;
    const int lane        = threadIdx.x & 31;
    const int n           = blockIdx.x * WARPS_PER_BLOCK + warp_in_blk;

    // y0 for this row: all lanes of the warp read the same float4 (broadcast)
    const float4 y0 = reinterpret_cast<const float4*>(y)[n];

    const float4* xp = reinterpret_cast<const float4*>(x) + (size_t)n * K_DIM;

    float m = 0.0f;
    #pragma unroll 8
    for (int i = 0; i < K_DIM / 32; ++i) {
        float4 v = __ldg(&xp[lane + 32 * i]);    // A/B: non-coherent path
        float dot = fabsf(v.x * y0.x + v.y * y0.y + v.z * y0.z + v.w * y0.w);
        m = fmaxf(m, dot);
    }

    // warp max-reduce
    #pragma unroll
    for (int off = 16; off > 0; off >>= 1)
        m = fmaxf(m, __shfl_xor_sync(0xFFFFFFFFu, m, off));

    __shared__ float s_d[WARPS_PER_BLOCK];
    if (lane == 0) {
        if (m > 0.9999999f) m = 1.0f;
        s_d[warp_in_blk] = 2.0f * acosf(m);
    }
    __syncthreads();

    __shared__ bool s_last;
    if (threadIdx.x == 0) {
        float t = 0.0f;
        #pragma unroll
        for (int i = 0; i < WARPS_PER_BLOCK; ++i) t += s_d[i];
        g_partials[blockIdx.x] = t;
        __threadfence();                               // publish partial
        unsigned int tk = atomicAdd(&g_ticket, 1u);
        s_last = (tk == NBLOCKS - 1);
    }
    __syncthreads();

    if (!s_last) return;

    // ---- last block: deterministic final reduction over g_partials ----
    const int tid = threadIdx.x;
    float t = 0.0f;
    #pragma unroll
    for (int i = tid; i < NBLOCKS; i += THREADS)
        t += __ldcg(&g_partials[i]);                   // L2-coherent read

    #pragma unroll
    for (int off = 16; off > 0; off >>= 1)
        t += __shfl_xor_sync(0xFFFFFFFFu, t, off);

    __shared__ float s_w[WARPS_PER_BLOCK];
    if (lane == 0) s_w[warp_in_blk] = t;
    __syncthreads();

    if (tid == 0) {
        float v = 0.0f;
        #pragma unroll
        for (int i = 0; i < WARPS_PER_BLOCK; ++i) v += s_w[i];
        out[0] = v / (float)N_ROWS;
        g_ticket = 0;                                  // reset for next replay
    }
}

extern "C" void kernel_launch(void* const* d_in, const int* in_sizes, int n_in,
                              void* d_out, int out_size)
{
    const float* y = (const float*)d_in[0];
    // d_in[1] = w_y : unused by the reference reduction
    const float* x = (const float*)d_in[2];
    float* out = (float*)d_out;

    fused_kernel<<<NBLOCKS, THREADS>>>(y, x, out);
}

// round 6
// speedup vs baseline: 1.0109x; 1.0109x over previous
#include <cuda_runtime.h>

// Problem: N=65536 rows. Per row n:
//   m = max_k |dot(x[n,k,:], y[n,0,:])|   (K=1024, D=4)
//   if m > 0.9999999 -> m = 1.0   (cost >= 0, so LOWER clamp is dead)
//   d[n] = 2*acos(m)              (acos monotone decreasing => min over k of
//                                  2*acos(cost) == 2*acos(max_k cost))
// out = sum(d) / N
//
// Inputs: d_in[0]=y (N,1,4) f32, d_in[1]=w_y (UNUSED), d_in[2]=x (N,K,4) f32.
// Output: 1 f32 scalar.
//
// Final configuration (measured best across 5 A/Bs):
//   - 8192 HW-scheduled blocks (natural waves beat persistent grid: 148 vs 154)
//   - warp-per-row, float4 __ldcs streaming (evict-first beat __ldg: 148 vs 152)
//   - single-level last-block ticket reduction (beat 2-level: 148 vs 150)
// DRAM 90.3% of peak, 7.16 TB/s — at the practical HBM roofline for this
// access mix; compulsory traffic 1.074 GB.

#define N_ROWS   65536
#define K_DIM    1024
#define WARPS_PER_BLOCK 8
#define THREADS  (WARPS_PER_BLOCK * 32)
#define NBLOCKS  (N_ROWS / WARPS_PER_BLOCK)   // 8192

__device__ float        g_partials[NBLOCKS];
__device__ unsigned int g_ticket = 0;          // self-resetting each launch

__global__ __launch_bounds__(THREADS)
void fused_kernel(const float* __restrict__ y,
                  const float* __restrict__ x,
                  float* __restrict__ out)
{
    const int warp_in_blk = threadIdx.x >> 5;
    const int lane        = threadIdx.x & 31;
    const int n           = blockIdx.x * WARPS_PER_BLOCK + warp_in_blk;

    // y0 for this row: all lanes of the warp read the same float4 (broadcast)
    const float4 y0 = reinterpret_cast<const float4*>(y)[n];

    const float4* xp = reinterpret_cast<const float4*>(x) + (size_t)n * K_DIM;

    float m = 0.0f;
    #pragma unroll 8
    for (int i = 0; i < K_DIM / 32; ++i) {
        float4 v = __ldcs(&xp[lane + 32 * i]);   // streamed once: evict-first
        float dot = fabsf(v.x * y0.x + v.y * y0.y + v.z * y0.z + v.w * y0.w);
        m = fmaxf(m, dot);
    }

    // warp max-reduce
    #pragma unroll
    for (int off = 16; off > 0; off >>= 1)
        m = fmaxf(m, __shfl_xor_sync(0xFFFFFFFFu, m, off));

    __shared__ float s_d[WARPS_PER_BLOCK];
    if (lane == 0) {
        if (m > 0.9999999f) m = 1.0f;
        s_d[warp_in_blk] = 2.0f * acosf(m);
    }
    __syncthreads();

    __shared__ bool s_last;
    if (threadIdx.x == 0) {
        float t = 0.0f;
        #pragma unroll
        for (int i = 0; i < WARPS_PER_BLOCK; ++i) t += s_d[i];
        g_partials[blockIdx.x] = t;
        __threadfence();                               // publish partial
        unsigned int tk = atomicAdd(&g_ticket, 1u);
        s_last = (tk == NBLOCKS - 1);
    }
    __syncthreads();

    if (!s_last) return;

    // ---- last block: deterministic final reduction over g_partials ----
    const int tid = threadIdx.x;
    float t = 0.0f;
    #pragma unroll
    for (int i = tid; i < NBLOCKS; i += THREADS)
        t += __ldcg(&g_partials[i]);                   // L2-coherent read

    #pragma unroll
    for (int off = 16; off > 0; off >>= 1)
        t += __shfl_xor_sync(0xFFFFFFFFu, t, off);

    __shared__ float s_w[WARPS_PER_BLOCK];
    if (lane == 0) s_w[warp_in_blk] = t;
    __syncthreads();

    if (tid == 0) {
        float v = 0.0f;
        #pragma unroll
        for (int i = 0; i < WARPS_PER_BLOCK; ++i) v += s_w[i];
        out[0] = v / (float)N_ROWS;
        g_ticket = 0;                                  // reset for next replay
    }
}

extern "C" void kernel_launch(void* const* d_in, const int* in_sizes, int n_in,
                              void* d_out, int out_size)
{
    const float* y = (const float*)d_in[0];
    // d_in[1] = w_y : unused by the reference reduction
    const float* x = (const float*)d_in[2];
    float* out = (float*)d_out;

    fused_kernel<<<NBLOCKS, THREADS>>>(y, x, out);
}

// round 7
// speedup vs baseline: 1.0135x; 1.0026x over previous
#include <cuda_runtime.h>

// Problem: N=65536 rows. Per row n:
//   m = max_k |dot(x[n,k,:], y[n,0,:])|   (K=1024, D=4)
//   if m > 0.9999999 -> m = 1.0   (cost >= 0, so LOWER clamp is dead)
//   d[n] = 2*acos(m)              (acos monotone decreasing => min over k of
//                                  2*acos(cost) == 2*acos(max_k cost))
// out = sum(d) / N
//
// Inputs: d_in[0]=y (N,1,4) f32, d_in[1]=w_y (UNUSED), d_in[2]=x (N,K,4) f32.
// Output: 1 f32 scalar.
//
// Structure: R2 winner (8192 HW-scheduled blocks, warp-per-row, __ldcs
// streaming) with the finalization collapsed to ONE packed u64 atomicAdd per
// block: low 50 bits = fixed-point (2^24) d-partial, bits >=50 = completion
// counter. Integer adds are associative -> deterministic. The last arriving
// block reconstructs the total from (returned_old + own_contribution) with
// zero extra memory traffic, writes out, and resets the accumulator for the
// next graph replay.

#define N_ROWS   65536
#define K_DIM    1024
#define WARPS_PER_BLOCK 8
#define THREADS  (WARPS_PER_BLOCK * 32)
#define NBLOCKS  (N_ROWS / WARPS_PER_BLOCK)   // 8192

#define FX_SCALE   16777216.0   // 2^24
#define CNT_SHIFT  50
#define FX_MASK    ((1ULL << CNT_SHIFT) - 1ULL)

__device__ unsigned long long g_acc = 0ULL;    // packed {counter, fixed-point sum}

__global__ __launch_bounds__(THREADS)
void fused_kernel(const float* __restrict__ y,
                  const float* __restrict__ x,
                  float* __restrict__ out)
{
    const int warp_in_blk = threadIdx.x >> 5;
    const int lane        = threadIdx.x & 31;
    const int n           = blockIdx.x * WARPS_PER_BLOCK + warp_in_blk;

    // y0 for this row: all lanes of the warp read the same float4 (broadcast)
    const float4 y0 = reinterpret_cast<const float4*>(y)[n];

    const float4* xp = reinterpret_cast<const float4*>(x) + (size_t)n * K_DIM;

    float m = 0.0f;
    #pragma unroll 8
    for (int i = 0; i < K_DIM / 32; ++i) {
        float4 v = __ldcs(&xp[lane + 32 * i]);   // streamed once: evict-first
        float dot = fabsf(v.x * y0.x + v.y * y0.y + v.z * y0.z + v.w * y0.w);
        m = fmaxf(m, dot);
    }

    // warp max-reduce
    #pragma unroll
    for (int off = 16; off > 0; off >>= 1)
        m = fmaxf(m, __shfl_xor_sync(0xFFFFFFFFu, m, off));

    __shared__ float s_d[WARPS_PER_BLOCK];
    if (lane == 0) {
        if (m > 0.9999999f) m = 1.0f;
        s_d[warp_in_blk] = 2.0f * acosf(m);
    }
    __syncthreads();

    if (threadIdx.x == 0) {
        float t = 0.0f;
        #pragma unroll
        for (int i = 0; i < WARPS_PER_BLOCK; ++i) t += s_d[i];

        // fixed-point contribution (exact f32 -> fixed via double), packed
        // with a completion count in the high bits. One atomic does it all.
        unsigned long long fx  = (unsigned long long)((double)t * FX_SCALE + 0.5);
        unsigned long long pkt = fx + (1ULL << CNT_SHIFT);
        unsigned long long old = atomicAdd(&g_acc, pkt);

        if ((old >> CNT_SHIFT) == (unsigned long long)(NBLOCKS - 1)) {
            // last block: total = old + own packet (no loads, no fences)
            unsigned long long total = (old + pkt) & FX_MASK;
            out[0] = (float)((double)total * (1.0 / FX_SCALE) / (double)N_ROWS);
            g_acc = 0ULL;                      // reset for next graph replay
        }
    }
}

extern "C" void kernel_launch(void* const* d_in, const int* in_sizes, int n_in,
                              void* d_out, int out_size)
{
    const float* y = (const float*)d_in[0];
    // d_in[1] = w_y : unused by the reference reduction
    const float* x = (const float*)d_in[2];
    float* out = (float*)d_out;

    fused_kernel<<<NBLOCKS, THREADS>>>(y, x, out);
}

// round 8
// speedup vs baseline: 1.0141x; 1.0006x over previous
#include <cuda_runtime.h>

// Problem: N=65536 rows. Per row n:
//   m = max_k |dot(x[n,k,:], y[n,0,:])|   (K=1024, D=4)
//   if m > 0.9999999 -> m = 1.0
//   d[n] = 2*acos(m)   (acos monotone decreasing => min 2*acos == 2*acos(max))
// out = sum(d) / N
//
// Inputs: d_in[0]=y (N,1,4) f32, d_in[1]=w_y (UNUSED), d_in[2]=x (N,K,4) f32.
// Output: 1 f32 scalar.
//
// Geometry A/B: 512-thread blocks (16 warps) x 4096 blocks, 4 blocks/SM —
// same 2048 threads/SM as the 256x8192 winner but half the scheduling units
// and half the block epilogues. Streaming via __ldcs (measured best), unroll
// 4 (lower front-batched MLP_p1 -> lower late-CTA spread per B300 model).
// Finalization: single packed u64 atomicAdd per block (R7, deterministic).

#define N_ROWS   65536
#define K_DIM    1024
#define WARPS_PER_BLOCK 16
#define THREADS  (WARPS_PER_BLOCK * 32)        // 512
#define NBLOCKS  (N_ROWS / WARPS_PER_BLOCK)    // 4096

#define FX_SCALE   16777216.0   // 2^24
#define CNT_SHIFT  50
#define FX_MASK    ((1ULL << CNT_SHIFT) - 1ULL)

__device__ unsigned long long g_acc = 0ULL;    // packed {counter, fixed-point sum}

__global__ __launch_bounds__(THREADS, 4)
void fused_kernel(const float* __restrict__ y,
                  const float* __restrict__ x,
                  float* __restrict__ out)
{
    const int warp_in_blk = threadIdx.x >> 5;
    const int lane        = threadIdx.x & 31;
    const int n           = blockIdx.x * WARPS_PER_BLOCK + warp_in_blk;

    // y0 for this row: all lanes of the warp read the same float4 (broadcast)
    const float4 y0 = reinterpret_cast<const float4*>(y)[n];

    const float4* xp = reinterpret_cast<const float4*>(x) + (size_t)n * K_DIM;

    float m = 0.0f;
    #pragma unroll 4
    for (int i = 0; i < K_DIM / 32; ++i) {
        float4 v = __ldcs(&xp[lane + 32 * i]);   // streamed once: evict-first
        float dot = fabsf(v.x * y0.x + v.y * y0.y + v.z * y0.z + v.w * y0.w);
        m = fmaxf(m, dot);
    }

    // warp max-reduce
    #pragma unroll
    for (int off = 16; off > 0; off >>= 1)
        m = fmaxf(m, __shfl_xor_sync(0xFFFFFFFFu, m, off));

    __shared__ float s_d[WARPS_PER_BLOCK];
    if (lane == 0) {
        if (m > 0.9999999f) m = 1.0f;
        s_d[warp_in_blk] = 2.0f * acosf(m);
    }
    __syncthreads();

    if (threadIdx.x == 0) {
        float t = 0.0f;
        #pragma unroll
        for (int i = 0; i < WARPS_PER_BLOCK; ++i) t += s_d[i];

        // fixed-point contribution (exact f32 -> fixed via double), packed
        // with a completion count in the high bits. One atomic does it all.
        unsigned long long fx  = (unsigned long long)((double)t * FX_SCALE + 0.5);
        unsigned long long pkt = fx + (1ULL << CNT_SHIFT);
        unsigned long long old = atomicAdd(&g_acc, pkt);

        if ((old >> CNT_SHIFT) == (unsigned long long)(NBLOCKS - 1)) {
            // last block: total = old + own packet (no loads, no fences)
            unsigned long long total = (old + pkt) & FX_MASK;
            out[0] = (float)((double)total * (1.0 / FX_SCALE) / (double)N_ROWS);
            g_acc = 0ULL;                      // reset for next graph replay
        }
    }
}

extern "C" void kernel_launch(void* const* d_in, const int* in_sizes, int n_in,
                              void* d_out, int out_size)
{
    const float* y = (const float*)d_in[0];
    // d_in[1] = w_y : unused by the reference reduction
    const float* x = (const float*)d_in[2];
    float* out = (float*)d_out;

    fused_kernel<<<NBLOCKS, THREADS>>>(y, x, out);
}

// round 9
// speedup vs baseline: 1.0231x; 1.0089x over previous
#include <cuda_runtime.h>

// SinkhornEvalKBestAbs — final converged kernel.
//
// Per row n (N=65536):
//   m = max_k |dot(x[n,k,:], y[n,0,:])|   (K=1024, D=4)
//   if m > 0.9999999 -> m = 1.0   (cost >= 0 so the LOWER clamp is dead)
//   d[n] = 2*acos(m)   (acos monotone decreasing => min_k 2*acos == 2*acos(max_k))
// out = sum(d) / N
//
// Inputs: d_in[0]=y (N,1,4) f32, d_in[1]=w_y (UNUSED), d_in[2]=x (N,K,4) f32.
// Output: 1 f32 scalar.
//
// Measured design ladder (GB300, sm_103a):
//   R2  256thr x 8192, __ldcs, ticket tail ........ 148.2 us, DRAM 90.3%
//   R3  persistent 1184 blocks .................... 153.6 us  (regression)
//   R4  2-level ticket ............................ 150.1 us  (neutral-)
//   R5  __ldg ..................................... 151.6 us  (regression)
//   R7  256thr + packed-atomic tail ............... 149.6 us  (neutral)
//   R8  512thr x 4096 ............................. 149.5 us  (neutral)
// => HBM-roofline-bound (~7.1 TB/s on 1.074 GB compulsory traffic).
// Final: R2 memory pattern (best DRAM%) + R7 epilogue (leanest: 1 atomic,
// no fences, no tail loads; integer fixed-point => deterministic).

#define N_ROWS   65536
#define K_DIM    1024
#define WARPS_PER_BLOCK 8
#define THREADS  (WARPS_PER_BLOCK * 32)       // 256
#define NBLOCKS  (N_ROWS / WARPS_PER_BLOCK)   // 8192

#define FX_SCALE   16777216.0   // 2^24
#define CNT_SHIFT  50
#define FX_MASK    ((1ULL << CNT_SHIFT) - 1ULL)

__device__ unsigned long long g_acc = 0ULL;   // packed {counter, fixed-point sum}

__global__ __launch_bounds__(THREADS)
void fused_kernel(const float* __restrict__ y,
                  const float* __restrict__ x,
                  float* __restrict__ out)
{
    const int warp_in_blk = threadIdx.x >> 5;
    const int lane        = threadIdx.x & 31;
    const int n           = blockIdx.x * WARPS_PER_BLOCK + warp_in_blk;

    // y0 for this row: all lanes of the warp read the same float4 (broadcast)
    const float4 y0 = reinterpret_cast<const float4*>(y)[n];

    const float4* xp = reinterpret_cast<const float4*>(x) + (size_t)n * K_DIM;

    float m = 0.0f;
    #pragma unroll 8
    for (int i = 0; i < K_DIM / 32; ++i) {
        float4 v = __ldcs(&xp[lane + 32 * i]);   // streamed once: evict-first
        float dot = fabsf(v.x * y0.x + v.y * y0.y + v.z * y0.z + v.w * y0.w);
        m = fmaxf(m, dot);
    }

    // warp max-reduce
    #pragma unroll
    for (int off = 16; off > 0; off >>= 1)
        m = fmaxf(m, __shfl_xor_sync(0xFFFFFFFFu, m, off));

    __shared__ float s_d[WARPS_PER_BLOCK];
    if (lane == 0) {
        if (m > 0.9999999f) m = 1.0f;
        s_d[warp_in_blk] = 2.0f * acosf(m);
    }
    __syncthreads();

    if (threadIdx.x == 0) {
        float t = 0.0f;
        #pragma unroll
        for (int i = 0; i < WARPS_PER_BLOCK; ++i) t += s_d[i];

        // Fixed-point contribution (exact f32 -> fixed via double), packed
        // with a completion count in the high bits. One atomic finalizes:
        // integer adds are associative => deterministic across arrivals.
        unsigned long long fx  = (unsigned long long)((double)t * FX_SCALE + 0.5);
        unsigned long long pkt = fx + (1ULL << CNT_SHIFT);
        unsigned long long old = atomicAdd(&g_acc, pkt);

        if ((old >> CNT_SHIFT) == (unsigned long long)(NBLOCKS - 1)) {
            // last block: total = old + own packet (no loads, no fences)
            unsigned long long total = (old + pkt) & FX_MASK;
            out[0] = (float)((double)total * (1.0 / FX_SCALE) / (double)N_ROWS);
            g_acc = 0ULL;                     // reset for next graph replay
        }
    }
}

extern "C" void kernel_launch(void* const* d_in, const int* in_sizes, int n_in,
                              void* d_out, int out_size)
{
    const float* y = (const float*)d_in[0];
    // d_in[1] = w_y : unused by the reference reduction
    const float* x = (const float*)d_in[2];
    float* out = (float*)d_out;

    fused_kernel<<<NBLOCKS, THREADS>>>(y, x, out);
}